// round 10
// baseline (speedup 1.0000x reference)
#include <cuda_runtime.h>
#include <cuda_fp16.h>
#include <cstdint>

// Inputs:
//  d_in[0] pts            float32  [N_PTS, 3]
//  d_in[1] p2v_idx        int32    [N_PTS]
//  d_in[2] embeddings     float32  [N_EMB, 16]
//  d_in[3] center_points  float32  [N_VOX, 3]
//  d_in[4] center2corner  int32    [N_VOX, 8]
//  d_in[5] voxel_size     float32  [1]
// Output: float32 [N_PTS, 16]
//
// Warp-per-voxel slotted layout: scatter points into <=8 fixed slots per
// voxel (overflow ~2% -> flat tail in same launch). Main kernel: warp = one
// voxel = 8 slots x 4-lane quads; every shared load (c2c, cp, 8 fp16 emb
// rows) is WARP-UNIFORM -> 1 L1 line each. emb wavefronts 8/pt -> 2/pt.
// fp16 emb table (rel_err ~2e-4 < 1e-3). 4 graph nodes.

#define N_EMB_MAX 1000000
#define N_VOX_MAX 500000
#define N_PTS_MAX 2000000
#define SLOTS 8

__device__ __align__(16) __half g_emb_h[N_EMB_MAX * 16];     // 32 MB
__device__ __align__(16) float4 g_cp4[N_VOX_MAX];            // 8 MB
__device__ int    g_cnt[N_VOX_MAX + 1];                      // +1 = ovf counter
__device__ __align__(16) float4 g_slot_pts[N_VOX_MAX * SLOTS]; // 64 MB
__device__ int    g_slot_pid[N_VOX_MAX * SLOTS];             // 16 MB
__device__ int    g_ovf_pid[N_PTS_MAX];                      // 8 MB

// ---- cache-hint helpers ----
__device__ __forceinline__ uint64_t make_evict_last_policy() {
    uint64_t pol;
    asm("createpolicy.fractional.L2::evict_last.b64 %0, 1.0;" : "=l"(pol));
    return pol;
}
__device__ __forceinline__ uint2 ldg_last_u2(const void* p, uint64_t pol) {
    uint2 v;
    asm volatile("ld.global.nc.L2::cache_hint.v2.b32 {%0,%1}, [%2], %3;"
                 : "=r"(v.x), "=r"(v.y) : "l"(p), "l"(pol));
    return v;
}
__device__ __forceinline__ float4 ldg_last_f4(const float4* p, uint64_t pol) {
    float4 v;
    asm volatile("ld.global.nc.L2::cache_hint.v4.f32 {%0,%1,%2,%3}, [%4], %5;"
                 : "=f"(v.x), "=f"(v.y), "=f"(v.z), "=f"(v.w)
                 : "l"(p), "l"(pol));
    return v;
}
__device__ __forceinline__ void ldg_last_i8(const int* p, int* o) {
    asm volatile("ld.global.nc.L2::evict_last.v8.b32 "
                 "{%0,%1,%2,%3,%4,%5,%6,%7}, [%8];"
                 : "=r"(o[0]), "=r"(o[1]), "=r"(o[2]), "=r"(o[3]),
                   "=r"(o[4]), "=r"(o[5]), "=r"(o[6]), "=r"(o[7])
                 : "l"(p));
}
__device__ __forceinline__ float4 ldg_stream_f4(const float4* p) {
    float4 v;
    asm volatile("ld.global.cs.v4.f32 {%0,%1,%2,%3}, [%4];"
                 : "=f"(v.x), "=f"(v.y), "=f"(v.z), "=f"(v.w) : "l"(p));
    return v;
}
__device__ __forceinline__ float ldg_stream_f(const float* p) {
    float v;
    asm volatile("ld.global.cs.f32 %0, [%1];" : "=f"(v) : "l"(p));
    return v;
}
__device__ __forceinline__ int ldg_stream_i(const int* p) {
    int v;
    asm volatile("ld.global.cs.s32 %0, [%1];" : "=r"(v) : "l"(p));
    return v;
}
__device__ __forceinline__ void stg_last_u4(void* p, uint4 v, uint64_t pol) {
    asm volatile("st.global.L2::cache_hint.v4.b32 [%0], {%1,%2,%3,%4}, %5;"
                 :: "l"(p), "r"(v.x), "r"(v.y), "r"(v.z), "r"(v.w), "l"(pol));
}
__device__ __forceinline__ void stg_last_f4(float4* p, float4 v, uint64_t pol) {
    asm volatile("st.global.L2::cache_hint.v4.f32 [%0], {%1,%2,%3,%4}, %5;"
                 :: "l"(p), "f"(v.x), "f"(v.y), "f"(v.z), "f"(v.w), "l"(pol));
}
__device__ __forceinline__ void stg_stream_f4(float4* p, float4 v) {
    asm volatile("st.global.cs.v4.f32 [%0], {%1,%2,%3,%4};"
                 :: "l"(p), "f"(v.x), "f"(v.y), "f"(v.z), "f"(v.w));
}

// ---- shared compute: interpolate one point from registers ----
// Identical instruction sequence in both paths -> bitwise-identical results.
__device__ __forceinline__ float4 interp_point(
    const uint2 r[8], float4 P, float4 cp, float inv_vs)
{
    float px = (P.x - cp.x) * inv_vs + 0.5f;
    float py = (P.y - cp.y) * inv_vs + 0.5f;
    float pz = (P.z - cp.z) * inv_vs + 0.5f;
    float wx[2] = {1.0f - px, px};
    float wy[2] = {1.0f - py, py};
    float wz[2] = {1.0f - pz, pz};
    float4 acc = make_float4(0.0f, 0.0f, 0.0f, 0.0f);
    #pragma unroll
    for (int c = 0; c < 8; ++c) {
        // corner c (meshgrid ij): bit2 -> x, bit1 -> y, bit0 -> z
        float w = wx[(c >> 2) & 1] * wy[(c >> 1) & 1] * wz[c & 1];
        float2 f01 = __half22float2(*reinterpret_cast<const __half2*>(&r[c].x));
        float2 f23 = __half22float2(*reinterpret_cast<const __half2*>(&r[c].y));
        acc.x = fmaf(w, f01.x, acc.x);
        acc.y = fmaf(w, f01.y, acc.y);
        acc.z = fmaf(w, f23.x, acc.z);
        acc.w = fmaf(w, f23.y, acc.w);
    }
    return acc;
}

__device__ __forceinline__ void load_rows(int v_cidx[8], int sub, uint64_t pol,
                                          uint2 r[8])
{
    #pragma unroll
    for (int c = 0; c < 8; ++c) {
        const char* rowp = reinterpret_cast<const char*>(g_emb_h)
                         + (size_t)v_cidx[c] * 32 + sub * 8;
        r[c] = ldg_last_u2(rowp, pol);
    }
}

// ---- k1: table prep: emb fp32->fp16, cp->float4 ----
__global__ void prep_kernel(const float* __restrict__ emb,
                            const float* __restrict__ cp,
                            int n8, int n_vox)
{
    int i = blockIdx.x * blockDim.x + threadIdx.x;
    uint64_t pol = make_evict_last_policy();
    if (i < n8) {
        const float4* src = reinterpret_cast<const float4*>(emb) + (size_t)i * 2;
        float4 a = ldg_stream_f4(&src[0]);
        float4 b = ldg_stream_f4(&src[1]);
        __half2 h0 = __floats2half2_rn(a.x, a.y);
        __half2 h1 = __floats2half2_rn(a.z, a.w);
        __half2 h2 = __floats2half2_rn(b.x, b.y);
        __half2 h3 = __floats2half2_rn(b.z, b.w);
        uint4 packed;
        packed.x = *reinterpret_cast<uint32_t*>(&h0);
        packed.y = *reinterpret_cast<uint32_t*>(&h1);
        packed.z = *reinterpret_cast<uint32_t*>(&h2);
        packed.w = *reinterpret_cast<uint32_t*>(&h3);
        stg_last_u4(reinterpret_cast<uint4*>(g_emb_h) + i, packed, pol);
        return;
    }
    int j = i - n8;
    if (j < n_vox) {
        float x = ldg_stream_f(&cp[3 * j + 0]);
        float y = ldg_stream_f(&cp[3 * j + 1]);
        float z = ldg_stream_f(&cp[3 * j + 2]);
        stg_last_f4(&g_cp4[j], make_float4(x, y, z, 0.0f), pol);
    }
}

// ---- k2: scatter points into per-voxel slots (overflow -> list) ----
__global__ void scatter_kernel(const int*   __restrict__ p2v,
                               const float* __restrict__ pts,
                               int n_pts, int n_vox)
{
    int i = blockIdx.x * blockDim.x + threadIdx.x;
    if (i >= n_pts) return;
    float x = ldg_stream_f(&pts[3 * i + 0]);
    float y = ldg_stream_f(&pts[3 * i + 1]);
    float z = ldg_stream_f(&pts[3 * i + 2]);
    int v = ldg_stream_i(&p2v[i]);
    int slot = atomicAdd(&g_cnt[v], 1);
    if (slot < SLOTS) {
        int s = v * SLOTS + slot;
        g_slot_pts[s] = make_float4(x, y, z, 0.0f);
        g_slot_pid[s] = i;
    } else {
        int o = atomicAdd(&g_cnt[n_vox], 1);
        g_ovf_pid[o] = i;
    }
}

// ---- k3: main — part A: warp per voxel; part B: flat overflow tail ----
__global__ void __launch_bounds__(256) voxel_interp_main_kernel(
    const int*    __restrict__ center2corner,
    const float*  __restrict__ pts,
    const int*    __restrict__ p2v_idx,
    const float*  __restrict__ voxel_size,
    float*        __restrict__ out,
    int n_vox, int n_pts, int nbA)
{
    uint64_t pol = make_evict_last_policy();
    float inv_vs = 1.0f / __ldg(&voxel_size[0]);

    if ((int)blockIdx.x < nbA) {
        // ---- part A: one warp per voxel, 8 slots x 4-lane quads ----
        int warp = threadIdx.x >> 5;
        int lane = threadIdx.x & 31;
        int v = blockIdx.x * 8 + warp;
        if (v >= n_vox) return;
        int slot = lane >> 2;
        int sub  = lane & 3;

        int cnt = __ldg(&g_cnt[v]);        // warp-uniform (1 line)
        if (cnt == 0) return;
        if (cnt > SLOTS) cnt = SLOTS;

        int cidx[8];
        ldg_last_i8(center2corner + (size_t)v * 8, cidx);  // uniform: 1 line
        float4 cp = ldg_last_f4(&g_cp4[v], pol);           // uniform: 1 sector

        uint2 r[8];
        load_rows(cidx, sub, pol, r);      // 8 instr x 1 line (warp-uniform rows)

        if (slot < cnt) {
            int si = v * SLOTS + slot;
            float4 P = __ldg(&g_slot_pts[si]);   // warp: 128B contiguous
            int pid  = __ldg(&g_slot_pid[si]);   // warp: 32B contiguous
            float4 acc = interp_point(r, P, cp, inv_vs);
            stg_stream_f4(reinterpret_cast<float4*>(out) + (size_t)pid * 4 + sub, acc);
        }
    } else {
        // ---- part B: flat path over overflow points ----
        int gtid = (blockIdx.x - nbA) * 256 + threadIdx.x;
        int idx  = gtid >> 2;
        int sub  = gtid & 3;
        int n_ovf = __ldg(&g_cnt[n_vox]);
        if (idx >= n_ovf) return;

        int p = __ldg(&g_ovf_pid[idx]);
        int v = ldg_stream_i(&p2v_idx[p]);

        int cidx[8];
        ldg_last_i8(center2corner + (size_t)v * 8, cidx);
        float4 cp = ldg_last_f4(&g_cp4[v], pol);
        float4 P  = make_float4(ldg_stream_f(&pts[3 * p + 0]),
                                ldg_stream_f(&pts[3 * p + 1]),
                                ldg_stream_f(&pts[3 * p + 2]), 0.0f);
        uint2 r[8];
        load_rows(cidx, sub, pol, r);
        float4 acc = interp_point(r, P, cp, inv_vs);
        stg_stream_f4(reinterpret_cast<float4*>(out) + (size_t)p * 4 + sub, acc);
    }
}

extern "C" void kernel_launch(void* const* d_in, const int* in_sizes, int n_in,
                              void* d_out, int out_size)
{
    const float* pts            = (const float*)d_in[0];
    const int*   p2v_idx        = (const int*)  d_in[1];
    const float* embeddings     = (const float*)d_in[2];
    const float* center_points  = (const float*)d_in[3];
    const int*   center2corner  = (const int*)  d_in[4];
    const float* voxel_size     = (const float*)d_in[5];
    float*       out            = (float*)d_out;

    int n8    = in_sizes[2] / 8;
    int n_vox = in_sizes[3] / 3;
    int n_pts = in_sizes[0] / 3;

    // node 1: zero counters (incl. overflow counter at index n_vox)
    void* cnt_ptr = nullptr;
    cudaGetSymbolAddress(&cnt_ptr, g_cnt);
    cudaMemsetAsync(cnt_ptr, 0, ((size_t)n_vox + 1) * sizeof(int));

    // node 2: tables
    int prep_threads = n8 + n_vox;
    prep_kernel<<<(prep_threads + 255) / 256, 256>>>(
        embeddings, center_points, n8, n_vox);

    // node 3: slot scatter
    scatter_kernel<<<(n_pts + 255) / 256, 256>>>(p2v_idx, pts, n_pts, n_vox);

    // node 4: main (part A: 8 voxels/block; part B: worst-case overflow tail)
    int nbA = (n_vox + 7) / 8;
    int nbB = (n_pts * 4 + 255) / 256;   // covers any overflow count
    voxel_interp_main_kernel<<<nbA + nbB, 256>>>(
        center2corner, pts, p2v_idx, voxel_size, out, n_vox, n_pts, nbA);
}

// round 11
// speedup vs baseline: 2.0720x; 2.0720x over previous
#include <cuda_runtime.h>
#include <cuda_fp16.h>
#include <cstdint>

// Inputs:
//  d_in[0] pts            float32  [N_PTS, 3]
//  d_in[1] p2v_idx        int32    [N_PTS]
//  d_in[2] embeddings     float32  [N_EMB, 16]
//  d_in[3] center_points  float32  [N_VOX, 3]
//  d_in[4] center2corner  int32    [N_VOX, 8]
//  d_in[5] voxel_size     float32  [1]
// Output: float32 [N_PTS, 16]
//
// Flat R6 structure (best so far) + pts component-per-lane shuffle:
// lane sub<3 loads pts[3p+sub] in ONE instruction (8 wavefronts/warp instead
// of 24 across 3 instructions), then 3 quad-wide shuffles broadcast x/y/z.
// fp16 emb table (rel_err ~2e-4 < 1e-3), L2 evict_last on gathered tables.

#define N_EMB_MAX 1000000
__device__ __align__(16) __half g_emb_h[N_EMB_MAX * 16];  // 32 MB

// ---- cache-hint helpers ----
__device__ __forceinline__ uint64_t make_evict_last_policy() {
    uint64_t pol;
    asm("createpolicy.fractional.L2::evict_last.b64 %0, 1.0;" : "=l"(pol));
    return pol;
}
__device__ __forceinline__ uint2 ldg_last_u2(const void* p, uint64_t pol) {
    uint2 v;
    asm volatile("ld.global.nc.L2::cache_hint.v2.b32 {%0,%1}, [%2], %3;"
                 : "=r"(v.x), "=r"(v.y) : "l"(p), "l"(pol));
    return v;
}
__device__ __forceinline__ float ldg_last_f(const float* p, uint64_t pol) {
    float v;
    asm volatile("ld.global.nc.L2::cache_hint.f32 %0, [%1], %2;"
                 : "=f"(v) : "l"(p), "l"(pol));
    return v;
}
__device__ __forceinline__ void ldg_last_i8(const int* p, int* o) {
    asm volatile("ld.global.nc.L2::evict_last.v8.b32 "
                 "{%0,%1,%2,%3,%4,%5,%6,%7}, [%8];"
                 : "=r"(o[0]), "=r"(o[1]), "=r"(o[2]), "=r"(o[3]),
                   "=r"(o[4]), "=r"(o[5]), "=r"(o[6]), "=r"(o[7])
                 : "l"(p));
}
__device__ __forceinline__ float4 ldg_stream_f4(const float4* p) {
    float4 v;
    asm volatile("ld.global.cs.v4.f32 {%0,%1,%2,%3}, [%4];"
                 : "=f"(v.x), "=f"(v.y), "=f"(v.z), "=f"(v.w) : "l"(p));
    return v;
}
__device__ __forceinline__ float ldg_stream_f(const float* p) {
    float v;
    asm volatile("ld.global.cs.f32 %0, [%1];" : "=f"(v) : "l"(p));
    return v;
}
__device__ __forceinline__ int ldg_stream_i(const int* p) {
    int v;
    asm volatile("ld.global.cs.s32 %0, [%1];" : "=r"(v) : "l"(p));
    return v;
}
__device__ __forceinline__ void stg_last_u4(void* p, uint4 v, uint64_t pol) {
    asm volatile("st.global.L2::cache_hint.v4.b32 [%0], {%1,%2,%3,%4}, %5;"
                 :: "l"(p), "r"(v.x), "r"(v.y), "r"(v.z), "r"(v.w), "l"(pol));
}
__device__ __forceinline__ void stg_last_f4(float4* p, float4 v, uint64_t pol) {
    asm volatile("st.global.L2::cache_hint.v4.f32 [%0], {%1,%2,%3,%4}, %5;"
                 :: "l"(p), "f"(v.x), "f"(v.y), "f"(v.z), "f"(v.w), "l"(pol));
}
__device__ __forceinline__ void stg_stream_f4(float4* p, float4 v) {
    asm volatile("st.global.cs.v4.f32 [%0], {%1,%2,%3,%4};"
                 :: "l"(p), "f"(v.x), "f"(v.y), "f"(v.z), "f"(v.w));
}

// ---- k1: table prep: emb fp32->fp16, cp->float4 ----
#define N_VOX_MAX 500000
__device__ __align__(16) float4 g_cp4[N_VOX_MAX];         // 8 MB

__global__ void prep_kernel(const float* __restrict__ emb,
                            const float* __restrict__ cp,
                            int n8, int n_vox)
{
    int i = blockIdx.x * blockDim.x + threadIdx.x;
    uint64_t pol = make_evict_last_policy();
    if (i < n8) {
        const float4* src = reinterpret_cast<const float4*>(emb) + (size_t)i * 2;
        float4 a = ldg_stream_f4(&src[0]);
        float4 b = ldg_stream_f4(&src[1]);
        __half2 h0 = __floats2half2_rn(a.x, a.y);
        __half2 h1 = __floats2half2_rn(a.z, a.w);
        __half2 h2 = __floats2half2_rn(b.x, b.y);
        __half2 h3 = __floats2half2_rn(b.z, b.w);
        uint4 packed;
        packed.x = *reinterpret_cast<uint32_t*>(&h0);
        packed.y = *reinterpret_cast<uint32_t*>(&h1);
        packed.z = *reinterpret_cast<uint32_t*>(&h2);
        packed.w = *reinterpret_cast<uint32_t*>(&h3);
        stg_last_u4(reinterpret_cast<uint4*>(g_emb_h) + i, packed, pol);
        return;
    }
    int j = i - n8;
    if (j < n_vox) {
        float x = ldg_stream_f(&cp[3 * j + 0]);
        float y = ldg_stream_f(&cp[3 * j + 1]);
        float z = ldg_stream_f(&cp[3 * j + 2]);
        stg_last_f4(&g_cp4[j], make_float4(x, y, z, 0.0f), pol);
    }
}

// ---- k2: main — 4 threads per point, pts via component shuffle ----
__global__ void __launch_bounds__(256) voxel_interp_kernel(
    const float*  __restrict__ pts,
    const int*    __restrict__ p2v_idx,
    const int*    __restrict__ center2corner,
    const float*  __restrict__ voxel_size,
    float*        __restrict__ out,
    int n_pts)
{
    int tid   = blockIdx.x * blockDim.x + threadIdx.x;
    int point = tid >> 2;
    int sub   = tid & 3;
    if (point >= n_pts) return;

    uint64_t pol = make_evict_last_policy();

    int v = ldg_stream_i(&p2v_idx[point]);

    // gather voxel data (warp instruction dedups identical quad addresses)
    int cidx[8];
    ldg_last_i8(center2corner + (size_t)v * 8, cidx);

    // cp4: each quad reads its voxel's padded center (16B, 1 sector)
    const float4* cp4p = &g_cp4[v];
    float4 cp;
    asm volatile("ld.global.nc.L2::cache_hint.v4.f32 {%0,%1,%2,%3}, [%4], %5;"
                 : "=f"(cp.x), "=f"(cp.y), "=f"(cp.z), "=f"(cp.w)
                 : "l"(cp4p), "l"(pol));

    // pts: ONE instruction — lane sub<3 loads component sub, then quad shuffle
    float comp = 0.0f;
    if (sub < 3) comp = ldg_stream_f(&pts[3 * (size_t)point + sub]);
    float Px = __shfl_sync(0xffffffffu, comp, 0, 4);
    float Py = __shfl_sync(0xffffffffu, comp, 1, 4);
    float Pz = __shfl_sync(0xffffffffu, comp, 2, 4);

    // batch all 8 embedding gathers before any FMA (MLP ~8)
    uint2 r[8];
    #pragma unroll
    for (int c = 0; c < 8; ++c) {
        const char* rowp = reinterpret_cast<const char*>(g_emb_h)
                         + (size_t)cidx[c] * 32 + sub * 8;
        r[c] = ldg_last_u2(rowp, pol);
    }

    float inv_vs = 1.0f / __ldg(&voxel_size[0]);
    float px = (Px - cp.x) * inv_vs + 0.5f;
    float py = (Py - cp.y) * inv_vs + 0.5f;
    float pz = (Pz - cp.z) * inv_vs + 0.5f;

    // corner c (meshgrid ij): bit2 -> x, bit1 -> y, bit0 -> z
    float wx[2] = {1.0f - px, px};
    float wy[2] = {1.0f - py, py};
    float wz[2] = {1.0f - pz, pz};

    float4 acc = make_float4(0.0f, 0.0f, 0.0f, 0.0f);
    #pragma unroll
    for (int c = 0; c < 8; ++c) {
        float w = wx[(c >> 2) & 1] * wy[(c >> 1) & 1] * wz[c & 1];
        float2 f01 = __half22float2(*reinterpret_cast<const __half2*>(&r[c].x));
        float2 f23 = __half22float2(*reinterpret_cast<const __half2*>(&r[c].y));
        acc.x = fmaf(w, f01.x, acc.x);
        acc.y = fmaf(w, f01.y, acc.y);
        acc.z = fmaf(w, f23.x, acc.z);
        acc.w = fmaf(w, f23.y, acc.w);
    }

    stg_stream_f4(reinterpret_cast<float4*>(out) + (size_t)point * 4 + sub, acc);
}

extern "C" void kernel_launch(void* const* d_in, const int* in_sizes, int n_in,
                              void* d_out, int out_size)
{
    const float* pts            = (const float*)d_in[0];
    const int*   p2v_idx        = (const int*)  d_in[1];
    const float* embeddings     = (const float*)d_in[2];
    const float* center_points  = (const float*)d_in[3];
    const int*   center2corner  = (const int*)  d_in[4];
    const float* voxel_size     = (const float*)d_in[5];
    float*       out            = (float*)d_out;

    int n8    = in_sizes[2] / 8;
    int n_vox = in_sizes[3] / 3;
    int n_pts = in_sizes[0] / 3;

    int prep_threads = n8 + n_vox;
    prep_kernel<<<(prep_threads + 255) / 256, 256>>>(
        embeddings, center_points, n8, n_vox);

    int total_threads = n_pts * 4;
    voxel_interp_kernel<<<(total_threads + 255) / 256, 256>>>(
        pts, p2v_idx, center2corner, voxel_size, out, n_pts);
}

// round 12
// speedup vs baseline: 2.1456x; 1.0355x over previous
#include <cuda_runtime.h>
#include <cuda_fp16.h>
#include <cstdint>

// Inputs:
//  d_in[0] pts            float32  [N_PTS, 3]
//  d_in[1] p2v_idx        int32    [N_PTS]
//  d_in[2] embeddings     float32  [N_EMB, 16]
//  d_in[3] center_points  float32  [N_VOX, 3]
//  d_in[4] center2corner  int32    [N_VOX, 8]
//  d_in[5] voxel_size     float32  [1]
// Output: float32 [N_PTS, 16]
//
// R11 (pts component shuffle, fp16 emb, evict_last hints) with occupancy
// reclaimed: __launch_bounds__(256, 8) pins 32 regs; weights computed and
// pts/cp consumed BEFORE the 8-row batch is live to shorten live ranges.

#define N_EMB_MAX 1000000
#define N_VOX_MAX 500000
__device__ __align__(16) __half g_emb_h[N_EMB_MAX * 16];  // 32 MB
__device__ __align__(16) float4 g_cp4[N_VOX_MAX];         // 8 MB

// ---- cache-hint helpers ----
__device__ __forceinline__ uint64_t make_evict_last_policy() {
    uint64_t pol;
    asm("createpolicy.fractional.L2::evict_last.b64 %0, 1.0;" : "=l"(pol));
    return pol;
}
__device__ __forceinline__ uint2 ldg_last_u2(const void* p, uint64_t pol) {
    uint2 v;
    asm volatile("ld.global.nc.L2::cache_hint.v2.b32 {%0,%1}, [%2], %3;"
                 : "=r"(v.x), "=r"(v.y) : "l"(p), "l"(pol));
    return v;
}
__device__ __forceinline__ float4 ldg_last_f4(const float4* p, uint64_t pol) {
    float4 v;
    asm volatile("ld.global.nc.L2::cache_hint.v4.f32 {%0,%1,%2,%3}, [%4], %5;"
                 : "=f"(v.x), "=f"(v.y), "=f"(v.z), "=f"(v.w)
                 : "l"(p), "l"(pol));
    return v;
}
__device__ __forceinline__ void ldg_last_i8(const int* p, int* o) {
    asm volatile("ld.global.nc.L2::evict_last.v8.b32 "
                 "{%0,%1,%2,%3,%4,%5,%6,%7}, [%8];"
                 : "=r"(o[0]), "=r"(o[1]), "=r"(o[2]), "=r"(o[3]),
                   "=r"(o[4]), "=r"(o[5]), "=r"(o[6]), "=r"(o[7])
                 : "l"(p));
}
__device__ __forceinline__ float4 ldg_stream_f4(const float4* p) {
    float4 v;
    asm volatile("ld.global.cs.v4.f32 {%0,%1,%2,%3}, [%4];"
                 : "=f"(v.x), "=f"(v.y), "=f"(v.z), "=f"(v.w) : "l"(p));
    return v;
}
__device__ __forceinline__ float ldg_stream_f(const float* p) {
    float v;
    asm volatile("ld.global.cs.f32 %0, [%1];" : "=f"(v) : "l"(p));
    return v;
}
__device__ __forceinline__ int ldg_stream_i(const int* p) {
    int v;
    asm volatile("ld.global.cs.s32 %0, [%1];" : "=r"(v) : "l"(p));
    return v;
}
__device__ __forceinline__ void stg_last_u4(void* p, uint4 v, uint64_t pol) {
    asm volatile("st.global.L2::cache_hint.v4.b32 [%0], {%1,%2,%3,%4}, %5;"
                 :: "l"(p), "r"(v.x), "r"(v.y), "r"(v.z), "r"(v.w), "l"(pol));
}
__device__ __forceinline__ void stg_last_f4(float4* p, float4 v, uint64_t pol) {
    asm volatile("st.global.L2::cache_hint.v4.f32 [%0], {%1,%2,%3,%4}, %5;"
                 :: "l"(p), "f"(v.x), "f"(v.y), "f"(v.z), "f"(v.w), "l"(pol));
}
__device__ __forceinline__ void stg_stream_f4(float4* p, float4 v) {
    asm volatile("st.global.cs.v4.f32 [%0], {%1,%2,%3,%4};"
                 :: "l"(p), "f"(v.x), "f"(v.y), "f"(v.z), "f"(v.w));
}

// ---- k1: table prep: emb fp32->fp16, cp->float4 ----
__global__ void prep_kernel(const float* __restrict__ emb,
                            const float* __restrict__ cp,
                            int n8, int n_vox)
{
    int i = blockIdx.x * blockDim.x + threadIdx.x;
    uint64_t pol = make_evict_last_policy();
    if (i < n8) {
        const float4* src = reinterpret_cast<const float4*>(emb) + (size_t)i * 2;
        float4 a = ldg_stream_f4(&src[0]);
        float4 b = ldg_stream_f4(&src[1]);
        __half2 h0 = __floats2half2_rn(a.x, a.y);
        __half2 h1 = __floats2half2_rn(a.z, a.w);
        __half2 h2 = __floats2half2_rn(b.x, b.y);
        __half2 h3 = __floats2half2_rn(b.z, b.w);
        uint4 packed;
        packed.x = *reinterpret_cast<uint32_t*>(&h0);
        packed.y = *reinterpret_cast<uint32_t*>(&h1);
        packed.z = *reinterpret_cast<uint32_t*>(&h2);
        packed.w = *reinterpret_cast<uint32_t*>(&h3);
        stg_last_u4(reinterpret_cast<uint4*>(g_emb_h) + i, packed, pol);
        return;
    }
    int j = i - n8;
    if (j < n_vox) {
        float x = ldg_stream_f(&cp[3 * j + 0]);
        float y = ldg_stream_f(&cp[3 * j + 1]);
        float z = ldg_stream_f(&cp[3 * j + 2]);
        stg_last_f4(&g_cp4[j], make_float4(x, y, z, 0.0f), pol);
    }
}

// ---- k2: main — 4 threads per point; weights computed before row batch ----
__global__ void __launch_bounds__(256, 8) voxel_interp_kernel(
    const float*  __restrict__ pts,
    const int*    __restrict__ p2v_idx,
    const int*    __restrict__ center2corner,
    const float*  __restrict__ voxel_size,
    float*        __restrict__ out,
    int n_pts)
{
    int tid   = blockIdx.x * blockDim.x + threadIdx.x;
    int point = tid >> 2;
    int sub   = tid & 3;
    if (point >= n_pts) return;

    uint64_t pol = make_evict_last_policy();
    float inv_vs = 1.0f / __ldg(&voxel_size[0]);

    int v = ldg_stream_i(&p2v_idx[point]);

    // pts: ONE instruction — lane sub<3 loads component sub, quad shuffle
    float comp = 0.0f;
    if (sub < 3) comp = ldg_stream_f(&pts[3 * (size_t)point + sub]);

    // cp4: quad reads its voxel's padded center (1 sector)
    float4 cp = ldg_last_f4(&g_cp4[v], pol);

    float Px = __shfl_sync(0xffffffffu, comp, 0, 4);
    float Py = __shfl_sync(0xffffffffu, comp, 1, 4);
    float Pz = __shfl_sync(0xffffffffu, comp, 2, 4);

    // weights FIRST: pts/cp die here, only 6 floats live across the batch
    float px = (Px - cp.x) * inv_vs + 0.5f;
    float py = (Py - cp.y) * inv_vs + 0.5f;
    float pz = (Pz - cp.z) * inv_vs + 0.5f;
    float wx[2] = {1.0f - px, px};
    float wy[2] = {1.0f - py, py};
    float wz[2] = {1.0f - pz, pz};

    int cidx[8];
    ldg_last_i8(center2corner + (size_t)v * 8, cidx);

    // batch all 8 embedding gathers (MLP ~8); cidx dies as addresses form
    uint2 r[8];
    #pragma unroll
    for (int c = 0; c < 8; ++c) {
        const char* rowp = reinterpret_cast<const char*>(g_emb_h)
                         + (size_t)cidx[c] * 32 + sub * 8;
        r[c] = ldg_last_u2(rowp, pol);
    }

    float4 acc = make_float4(0.0f, 0.0f, 0.0f, 0.0f);
    #pragma unroll
    for (int c = 0; c < 8; ++c) {
        // corner c (meshgrid ij): bit2 -> x, bit1 -> y, bit0 -> z
        float w = wx[(c >> 2) & 1] * wy[(c >> 1) & 1] * wz[c & 1];
        float2 f01 = __half22float2(*reinterpret_cast<const __half2*>(&r[c].x));
        float2 f23 = __half22float2(*reinterpret_cast<const __half2*>(&r[c].y));
        acc.x = fmaf(w, f01.x, acc.x);
        acc.y = fmaf(w, f01.y, acc.y);
        acc.z = fmaf(w, f23.x, acc.z);
        acc.w = fmaf(w, f23.y, acc.w);
    }

    stg_stream_f4(reinterpret_cast<float4*>(out) + (size_t)point * 4 + sub, acc);
}

extern "C" void kernel_launch(void* const* d_in, const int* in_sizes, int n_in,
                              void* d_out, int out_size)
{
    const float* pts            = (const float*)d_in[0];
    const int*   p2v_idx        = (const int*)  d_in[1];
    const float* embeddings     = (const float*)d_in[2];
    const float* center_points  = (const float*)d_in[3];
    const int*   center2corner  = (const int*)  d_in[4];
    const float* voxel_size     = (const float*)d_in[5];
    float*       out            = (float*)d_out;

    int n8    = in_sizes[2] / 8;
    int n_vox = in_sizes[3] / 3;
    int n_pts = in_sizes[0] / 3;

    int prep_threads = n8 + n_vox;
    prep_kernel<<<(prep_threads + 255) / 256, 256>>>(
        embeddings, center_points, n8, n_vox);

    int total_threads = n_pts * 4;
    voxel_interp_kernel<<<(total_threads + 255) / 256, 256>>>(
        pts, p2v_idx, center2corner, voxel_size, out, n_pts);
}